// round 1
// baseline (speedup 1.0000x reference)
#include <cuda_runtime.h>

#define MM   128   // padded image side
#define NP   64    // patch side
#define NC   4     // channels / positions
#define C0   32    // (M - N) / 2

__global__ __launch_bounds__(512, 3)
void extract_patches_kernel(const float* __restrict__ img,
                            const float* __restrict__ pos,
                            float* __restrict__ out)
{
    const int b = blockIdx.x;
    const float* I = img + (size_t)b * (MM * MM);
    float4* out4 = reinterpret_cast<float4*>(out) + (size_t)b * (NP * NP);

    // Stage the 8 position scalars for this batch: layout (B,1,2,C),
    // dim 0 = ox (x shift), dim 1 = oy (y shift).
    __shared__ float sox[NC], soy[NC];
    if (threadIdx.y == 0 && threadIdx.x < 2 * NC) {
        float v = pos[(size_t)b * (2 * NC) + threadIdx.x];
        if (threadIdx.x < NC) sox[threadIdx.x] = v;
        else                  soy[threadIdx.x - NC] = v;
    }
    __syncthreads();

    const int tx = threadIdx.x;  // output column j in [0, 64)

    // Per-channel horizontal sample position: xx = (j + 32) + ox  (matches
    // reference rounding: integer + fp32 add, then floor).
    float wx[NC];
    int   xi[NC];
#pragma unroll
    for (int c = 0; c < NC; c++) {
        float xx = (float)(tx + C0) + sox[c];
        float x0 = floorf(xx);
        wx[c] = xx - x0;
        xi[c] = (int)x0;
    }

    // Rows: 8 threads in y, each handles 8 of the 64 output rows.
    for (int i = threadIdx.y; i < NP; i += 8) {
        float4 res;
        float* rp = reinterpret_cast<float*>(&res);
#pragma unroll
        for (int c = 0; c < NC; c++) {
            float yy = (float)(i + C0) + soy[c];
            float y0 = floorf(yy);
            float wy = yy - y0;
            int   yi = (int)y0;

            // With SHIFT_MAX=20, c0=32, N=64, M=128: yi in [12,51],
            // yi+64 <= 115 < 128 — the reference's valid-mask is always
            // true, so no bounds checks are needed.
            const float* p = I + yi * MM + xi[c];
            float v00 = __ldg(p);
            float v01 = __ldg(p + 1);
            float v10 = __ldg(p + MM);
            float v11 = __ldg(p + MM + 1);

            float wxc = wx[c];
            float top = fmaf(v01 - v00, wxc, v00);
            float bot = fmaf(v11 - v10, wxc, v10);
            rp[c] = fmaf(bot - top, wy, top);
        }
        out4[i * NP + tx] = res;  // coalesced 128-bit store, channel-innermost
    }
}

extern "C" void kernel_launch(void* const* d_in, const int* in_sizes, int n_in,
                              void* d_out, int out_size)
{
    const float* img = (const float*)d_in[0];   // padded_obj (B,128,128,1)
    const float* pos = (const float*)d_in[1];   // positions  (B,1,2,4)
    float* out = (float*)d_out;                 // (B,64,64,4)

    int B = in_sizes[0] / (MM * MM);
    dim3 block(64, 8);
    extract_patches_kernel<<<B, block>>>(img, pos, out);
}

// round 2
// speedup vs baseline: 1.2313x; 1.2313x over previous
#include <cuda_runtime.h>

#define MM   128   // padded image side
#define NP   64    // patch side
#define NC   4     // channels / positions
#define C0   32    // (M - N) / 2

__global__ __launch_bounds__(512, 2)
void extract_patches_kernel(const float* __restrict__ img,
                            const float* __restrict__ pos,
                            float* __restrict__ out)
{
    const int b = blockIdx.x;
    const float* I = img + (size_t)b * (MM * MM);
    float4* out4 = reinterpret_cast<float4*>(out) + (size_t)b * (NP * NP);

    // Stage the 8 position scalars: layout (B,1,2,C); dim0 = ox, dim1 = oy.
    __shared__ float spos[2 * NC];
    if (threadIdx.y == 0 && threadIdx.x < 2 * NC)
        spos[threadIdx.x] = pos[(size_t)b * (2 * NC) + threadIdx.x];
    __syncthreads();

    const int tx = threadIdx.x;        // output column j in [0, 64)
    const int i0 = threadIdx.y * 8;    // this thread's contiguous row band

    // Per-channel setup: horizontal weight/index (constant over the band),
    // initial vertical index, and the horizontally-lerped TOP row (hprev).
    float wx[NC], hprev[NC], yif[NC], oyv[NC];
    int   off[NC];
#pragma unroll
    for (int c = 0; c < NC; c++) {
        float ox = spos[c];
        oyv[c]   = spos[NC + c];

        float xx = (float)(tx + C0) + ox;
        float x0 = floorf(xx);
        wx[c]    = xx - x0;
        int xi   = (int)x0;

        float yy = (float)(i0 + C0) + oyv[c];
        float y0 = floorf(yy);
        yif[c]   = y0;
        int yi   = (int)y0;

        // SHIFT_MAX=20, c0=32: yi in [12,51], xi in [12,51]; deepest access
        // yi+8 rows / xi+1 cols stays < 128 -> reference valid-mask always true.
        off[c] = yi * MM + xi;
        float a0 = __ldg(I + off[c]);
        float a1 = __ldg(I + off[c] + 1);
        hprev[c] = fmaf(a1 - a0, wx[c], a0);   // H(top row)
    }

    // Walk 8 contiguous rows; each step loads only the new BOTTOM row taps
    // (2 per channel) and reuses hprev as the top H-row.
#pragma unroll
    for (int k = 0; k < 8; k++) {
        float4 res;
        float* rp = reinterpret_cast<float*>(&res);
#pragma unroll
        for (int c = 0; c < NC; c++) {
            off[c] += MM;
            float b0 = __ldg(I + off[c]);
            float b1 = __ldg(I + off[c] + 1);
            float hnew = fmaf(b1 - b0, wx[c], b0);      // H(bottom row)

            // wy per-row, matching the reference's yy = (i+c0)+oy arithmetic.
            float yy = (float)(i0 + k + C0) + oyv[c];
            float wy = yy - (yif[c] + (float)k);

            rp[c]    = fmaf(hnew - hprev[c], wy, hprev[c]);
            hprev[c] = hnew;
        }
        out4[(i0 + k) * NP + tx] = res;   // coalesced 128-bit store
    }
}

extern "C" void kernel_launch(void* const* d_in, const int* in_sizes, int n_in,
                              void* d_out, int out_size)
{
    const float* img = (const float*)d_in[0];   // padded_obj (B,128,128,1)
    const float* pos = (const float*)d_in[1];   // positions  (B,1,2,4)
    float* out = (float*)d_out;                 // (B,64,64,4)

    int B = in_sizes[0] / (MM * MM);
    dim3 block(64, 8);
    extract_patches_kernel<<<B, block>>>(img, pos, out);
}